// round 6
// baseline (speedup 1.0000x reference)
#include <cuda_runtime.h>
#include <cuda_bf16.h>
#include <math.h>

// ---------------- constants ----------------
#define BATCH   32
#define HDIM    2048
#define NHEADS  16
#define HEADD   128
#define DFF     8192
#define QKV_N   (3*HDIM)   // 6144
#define MAXS    2048
#define MAXBLK  32
#define PAGE    64
#define NUMBLK  1024
#define NSPLIT  32
#define CHUNK   64         // MAXS / NSPLIT == one KV page
#define TKC     32         // gemm k-chunk
#define TN      128        // gemm n-tile
#define NSTAGE  3          // gemm pipeline stages

// ---------------- scratch (no allocs allowed) ----------------
__device__ float g_x1 [BATCH*HDIM];
__device__ float g_qkv[BATCH*QKV_N];
__device__ float g_att[BATCH*HDIM];
__device__ float g_h  [BATCH*HDIM];
__device__ float g_x2 [BATCH*HDIM];
__device__ float g_ffn[BATCH*DFF];
__device__ float g_pm [BATCH*NHEADS*NSPLIT];
__device__ float g_ps [BATCH*NHEADS*NSPLIT];
__device__ float g_pa [BATCH*NHEADS*NSPLIT*HEADD];

// ---------------- helpers ----------------
__device__ __forceinline__ float gelu_exact(float x) {
    return 0.5f * x * (1.0f + erff(x * 0.70710678118654752f));
}

__device__ __forceinline__ void split_tf32(float x, unsigned &hi, unsigned &lo) {
    unsigned h;
    asm("cvt.rna.tf32.f32 %0, %1;" : "=r"(h) : "f"(x));
    hi = h;
    lo = __float_as_uint(x - __uint_as_float(h));
}

__device__ __forceinline__ void mma_tf32(float d[4], const unsigned a[4],
                                         unsigned b0, unsigned b1) {
    asm volatile(
        "mma.sync.aligned.m16n8k8.row.col.f32.tf32.tf32.f32 "
        "{%0,%1,%2,%3}, {%4,%5,%6,%7}, {%8,%9}, {%0,%1,%2,%3};"
        : "+f"(d[0]), "+f"(d[1]), "+f"(d[2]), "+f"(d[3])
        : "r"(a[0]), "r"(a[1]), "r"(a[2]), "r"(a[3]), "r"(b0), "r"(b1));
}

__device__ __forceinline__ void cp_async16(void* smem, const void* g) {
    unsigned s = (unsigned)__cvta_generic_to_shared(smem);
    asm volatile("cp.async.cg.shared.global [%0], [%1], 16;" :: "r"(s), "l"(g));
}
__device__ __forceinline__ void cp_commit() {
    asm volatile("cp.async.commit_group;");
}
template<int N>
__device__ __forceinline__ void cp_wait() {
    asm volatile("cp.async.wait_group %0;" :: "n"(N));
}

// ---------------- LayerNorm: 32 rows x 2048 ----------------
__global__ void __launch_bounds__(256) ln_kernel(
    const float* __restrict__ x, const float* __restrict__ g,
    const float* __restrict__ b, float* __restrict__ y)
{
    int row = blockIdx.x;
    const float* xr = x + row * HDIM;
    float s = 0.f, s2 = 0.f;
    for (int i = threadIdx.x; i < HDIM; i += 256) {
        float v = xr[i]; s += v; s2 += v * v;
    }
    __shared__ float sh[16];
    int lane = threadIdx.x & 31, w = threadIdx.x >> 5;
    #pragma unroll
    for (int o = 16; o; o >>= 1) {
        s  += __shfl_xor_sync(0xffffffffu, s,  o);
        s2 += __shfl_xor_sync(0xffffffffu, s2, o);
    }
    if (lane == 0) { sh[w] = s; sh[8 + w] = s2; }
    __syncthreads();
    if (threadIdx.x == 0) {
        float S = 0.f, S2 = 0.f;
        #pragma unroll
        for (int i = 0; i < 8; i++) { S += sh[i]; S2 += sh[8 + i]; }
        sh[0] = S; sh[1] = S2;
    }
    __syncthreads();
    float mu  = sh[0] * (1.0f / HDIM);
    float var = sh[1] * (1.0f / HDIM) - mu * mu;
    float inv = rsqrtf(var + 1e-5f);
    float* yr = y + row * HDIM;
    for (int i = threadIdx.x; i < HDIM; i += 256)
        yr[i] = (xr[i] - mu) * inv * g[i] + b[i];
}

// ---------------- merged init: qkv=b, h=b+res, ffn=b ----------------
__global__ void __launch_bounds__(256) init3_kernel(
    float* __restrict__ qkv, const float* __restrict__ battn,
    float* __restrict__ h, const float* __restrict__ bproj,
    const float* __restrict__ hidden,
    float* __restrict__ ffn, const float* __restrict__ bfc)
{
    const int n1 = BATCH * QKV_N;
    const int n2 = n1 + BATCH * HDIM;
    const int n3 = n2 + BATCH * DFF;
    for (int i = blockIdx.x * 256 + threadIdx.x; i < n3; i += gridDim.x * 256) {
        if (i < n1) {
            qkv[i] = battn[i % QKV_N];
        } else if (i < n2) {
            int j = i - n1;
            h[j] = bproj[j & (HDIM - 1)] + hidden[j];
        } else {
            int j = i - n2;
            ffn[j] = bfc[j & (DFF - 1)];
        }
    }
}

__global__ void init_kernel(float* __restrict__ C, const float* __restrict__ bias,
                            const float* __restrict__ res, int N, int total)
{
    for (int i = blockIdx.x * blockDim.x + threadIdx.x; i < total;
         i += gridDim.x * blockDim.x) {
        int col = i - (i / N) * N;
        float v = bias[col];
        if (res) v += res[i];
        C[i] = v;
    }
}

// ---------------- elementwise gelu (in place, float4) ----------------
__global__ void gelu_kernel(float* __restrict__ x, int n4)
{
    int i = blockIdx.x * 256 + threadIdx.x;
    if (i < n4) {
        float4 v = reinterpret_cast<float4*>(x)[i];
        v.x = gelu_exact(v.x); v.y = gelu_exact(v.y);
        v.z = gelu_exact(v.z); v.w = gelu_exact(v.w);
        reinterpret_cast<float4*>(x)[i] = v;
    }
}

// ---------------- tensor-core GEMM: C[32,N] += A[32,K] @ W[K,N] ----------------
// 3xTF32, 3-stage cp.async ring, 2 CTAs/SM. 256 thr = 8 warps: 2(m16) x 4(n32).
// split-K via gridDim.y, atomicAdd into bias-preinitialized C.
#define WS_FL (TKC*136)
#define AS_FL (32*36)
#define GEMM_SMEM (NSTAGE*(WS_FL+AS_FL)*4)
__global__ void __launch_bounds__(256, 2) gemm_tc(
    const float* __restrict__ A, const float* __restrict__ W,
    float* __restrict__ C, int K, int N)
{
    extern __shared__ float smp[];
    float (*Ws)[TKC][136] = reinterpret_cast<float(*)[TKC][136]>(smp);
    float (*As)[32][36]   = reinterpret_cast<float(*)[32][36]>(smp + NSTAGE * WS_FL);

    int tid = threadIdx.x;
    int lane = tid & 31, warp = tid >> 5;
    int m0 = (warp & 1) * 16;
    int n0w = (warp >> 1) * 32;
    int nblk = blockIdx.x * TN;

    int kc = K / gridDim.y;
    int kbeg = blockIdx.y * kc;
    int nchunk = kc / TKC;

    float acc[4][4] = {};

    int am = tid >> 3, ak = (tid & 7) * 4;   // A staging coords (1 seg/thread)
    int gr = lane >> 2, kq = lane & 3;       // fragment coords

    auto prefetch = [&](int chunk) {
        int kb = kbeg + chunk * TKC;
        int s = chunk % NSTAGE;
        cp_async16(&As[s][am][ak], &A[am * K + kb + ak]);
        #pragma unroll
        for (int it = 0; it < 4; ++it) {
            int idx = it * 256 + tid;
            int kk = idx >> 5, c4 = (idx & 31) * 4;
            cp_async16(&Ws[s][kk][c4], &W[(size_t)(kb + kk) * N + nblk + c4]);
        }
    };

    #pragma unroll
    for (int c = 0; c < NSTAGE - 1; ++c) {
        if (c < nchunk) prefetch(c);
        cp_commit();
    }

    for (int i = 0; i < nchunk; ++i) {
        if (i + NSTAGE - 1 < nchunk) prefetch(i + NSTAGE - 1);
        cp_commit();
        cp_wait<NSTAGE - 1>();
        __syncthreads();
        int s = i % NSTAGE;
        #pragma unroll
        for (int ks = 0; ks < 4; ++ks) {
            int k0 = ks * 8;
            unsigned ah[4], al[4];
            split_tf32(As[s][m0 + gr    ][k0 + kq    ], ah[0], al[0]);
            split_tf32(As[s][m0 + gr + 8][k0 + kq    ], ah[1], al[1]);
            split_tf32(As[s][m0 + gr    ][k0 + kq + 4], ah[2], al[2]);
            split_tf32(As[s][m0 + gr + 8][k0 + kq + 4], ah[3], al[3]);
            #pragma unroll
            for (int nt = 0; nt < 4; ++nt) {
                int nb2 = n0w + nt * 8 + gr;
                unsigned bh0, bl0, bh1, bl1;
                split_tf32(Ws[s][k0 + kq    ][nb2], bh0, bl0);
                split_tf32(Ws[s][k0 + kq + 4][nb2], bh1, bl1);
                mma_tf32(acc[nt], ah, bh0, bh1);
                mma_tf32(acc[nt], ah, bl0, bl1);
                mma_tf32(acc[nt], al, bh0, bh1);
            }
        }
        __syncthreads();   // all reads done before ring slot is overwritten
    }

    int cq = (lane & 3) * 2;
    #pragma unroll
    for (int nt = 0; nt < 4; ++nt) {
        int col = nblk + n0w + nt * 8 + cq;
        atomicAdd(&C[(m0 + gr    ) * N + col    ], acc[nt][0]);
        atomicAdd(&C[(m0 + gr    ) * N + col + 1], acc[nt][1]);
        atomicAdd(&C[(m0 + gr + 8) * N + col    ], acc[nt][2]);
        atomicAdd(&C[(m0 + gr + 8) * N + col + 1], acc[nt][3]);
    }
}

// ---------------- attention partial: one block per (b,h,page) ----------------
// V page is bulk-prefetched via cp.async while K is scored; pass 2 reads smem.
__global__ void __launch_bounds__(256) attn_partial(
    const float* __restrict__ qkv, const float* __restrict__ kv,
    const int* __restrict__ bt, const int* __restrict__ sl,
    float* __restrict__ pm, float* __restrict__ ps, float* __restrict__ pa)
{
    int b = blockIdx.x, h = blockIdx.y, sp = blockIdx.z;
    int tid = threadIdx.x, lane = tid & 31, w = tid >> 5;
    int pidx = (b * NHEADS + h) * NSPLIT + sp;
    int seq = sl[b];
    int t0 = sp * CHUNK;
    if (t0 >= seq) {
        if (tid == 0) { pm[pidx] = -INFINITY; ps[pidx] = 0.f; }
        return;
    }
    int nt = seq - t0; if (nt > CHUNK) nt = CHUNK;

    __shared__ float qs[HEADD];
    __shared__ float sc[CHUNK];
    __shared__ float red[9];
    __shared__ float sa[2][HEADD];
    __shared__ __align__(16) float Vs[CHUNK][HEADD];   // 32 KB

    // page row base (float index, < 2^31). Broadcast LDG.
    int rb = bt[b * MAXBLK + sp] * (PAGE * NHEADS * HEADD) + h * HEADD;

    // kick off V prefetch: whole page-head slice, 8 x 16B per thread
    {
        const float* Vb = kv + (size_t)NUMBLK * PAGE * NHEADS * HEADD + rb;
        #pragma unroll
        for (int i = 0; i < 8; ++i) {
            int seg = tid + i * 256;         // 2048 segs of 16B
            int t = seg >> 5, off = (seg & 31) * 4;
            cp_async16(&Vs[t][off], Vb + t * (NHEADS * HEADD) + off);
        }
        cp_commit();
    }

    if (tid < HEADD) qs[tid] = qkv[b * QKV_N + h * HEADD + tid];
    __syncthreads();

    const float scale = 0.08838834764831845f;  // 1/sqrt(128)
    float4 qx = reinterpret_cast<const float4*>(qs)[lane];

    // pass 1: scores. 8 warps, 2 tokens/warp/iter, full-warp shfl reduce.
    for (int t = w * 2; t < nt; t += 16) {
        const float* k0p = kv + rb + t * (NHEADS * HEADD);
        float4 ka = reinterpret_cast<const float4*>(k0p)[lane];
        bool two = (t + 1) < nt;
        const float* k1p = k0p + (NHEADS * HEADD);
        float4 kb2 = two ? reinterpret_cast<const float4*>(k1p)[lane] : ka;
        float d0 = ka.x * qx.x + ka.y * qx.y + ka.z * qx.z + ka.w * qx.w;
        float d1 = kb2.x * qx.x + kb2.y * qx.y + kb2.z * qx.z + kb2.w * qx.w;
        #pragma unroll
        for (int o = 16; o; o >>= 1) {
            d0 += __shfl_xor_sync(0xffffffffu, d0, o);
            d1 += __shfl_xor_sync(0xffffffffu, d1, o);
        }
        if (lane == 0) {
            sc[t] = d0 * scale;
            if (two) sc[t + 1] = d1 * scale;
        }
    }
    __syncthreads();

    // local max
    float m = -INFINITY;
    if (tid < nt) m = sc[tid];
    #pragma unroll
    for (int o = 16; o; o >>= 1) m = fmaxf(m, __shfl_xor_sync(0xffffffffu, m, o));
    if (lane == 0) red[w] = m;
    __syncthreads();
    if (tid == 0) {
        float mm = red[0];
        #pragma unroll
        for (int i = 1; i < 8; i++) mm = fmaxf(mm, red[i]);
        red[8] = mm;
    }
    __syncthreads();
    float M = red[8];
    __syncthreads();

    // exp + local sum
    float s = 0.f;
    if (tid < nt) {
        float e = __expf(sc[tid] - M);
        sc[tid] = e; s = e;
    }
    #pragma unroll
    for (int o = 16; o; o >>= 1) s += __shfl_xor_sync(0xffffffffu, s, o);
    if (lane == 0) red[w] = s;
    __syncthreads();
    if (tid == 0) {
        float S = 0.f;
        #pragma unroll
        for (int i = 0; i < 8; i++) S += red[i];
        pm[pidx] = M; ps[pidx] = S;
    }

    // pass 2: weighted V from smem. 2 halves x 4-way unroll.
    cp_wait<0>();
    __syncthreads();
    int d = tid & 127, half = tid >> 7;
    float a0 = 0.f, a1 = 0.f, a2 = 0.f, a3 = 0.f;
    int t = half;
    for (; t + 6 < nt; t += 8) {
        a0 += sc[t    ] * Vs[t    ][d];
        a1 += sc[t + 2] * Vs[t + 2][d];
        a2 += sc[t + 4] * Vs[t + 4][d];
        a3 += sc[t + 6] * Vs[t + 6][d];
    }
    for (; t < nt; t += 2) a0 += sc[t] * Vs[t][d];
    sa[half][d] = (a0 + a1) + (a2 + a3);
    __syncthreads();
    if (tid < HEADD) pa[(size_t)pidx * HEADD + tid] = sa[0][tid] + sa[1][tid];
}

// ---------------- attention combine: one block per (b,h) ----------------
__global__ void __launch_bounds__(128) attn_combine(
    const float* __restrict__ pm, const float* __restrict__ ps,
    const float* __restrict__ pa, float* __restrict__ out)
{
    int b = blockIdx.x, h = blockIdx.y;
    int idx = b * NHEADS + h;
    int tid = threadIdx.x;
    __shared__ float ms[NSPLIT], ss[NSPLIT];
    if (tid < NSPLIT) {
        ms[tid] = pm[idx * NSPLIT + tid];
        ss[tid] = ps[idx * NSPLIT + tid];
    }
    __syncthreads();
    float M = -INFINITY;
    #pragma unroll
    for (int i = 0; i < NSPLIT; i++)
        if (ss[i] > 0.f) M = fmaxf(M, ms[i]);
    float num = 0.f, den = 0.f;
    #pragma unroll
    for (int i = 0; i < NSPLIT; i++) {
        if (ss[i] > 0.f) {
            float wv = __expf(ms[i] - M);
            den += wv * ss[i];
            num += wv * pa[((size_t)idx * NSPLIT + i) * HEADD + tid];
        }
    }
    out[b * HDIM + h * HEADD + tid] = num / den;
}

// ---------------- host launcher ----------------
extern "C" void kernel_launch(void* const* d_in, const int* in_sizes, int n_in,
                              void* d_out, int out_size)
{
    const float* hidden = (const float*)d_in[0];
    const float* kv     = (const float*)d_in[1];
    const int*   bt     = (const int*)d_in[2];
    const int*   sl     = (const int*)d_in[3];
    int p = (n_in > 4 && in_sizes[4] == 1) ? 5 : 4;  // skip max_seq_len if present
    const float* ln1g  = (const float*)d_in[p + 0];
    const float* ln1b  = (const float*)d_in[p + 1];
    const float* ln2g  = (const float*)d_in[p + 2];
    const float* ln2b  = (const float*)d_in[p + 3];
    const float* wattn = (const float*)d_in[p + 4];
    const float* battn = (const float*)d_in[p + 5];
    const float* wproj = (const float*)d_in[p + 6];
    const float* bproj = (const float*)d_in[p + 7];
    const float* wfc   = (const float*)d_in[p + 8];
    const float* bfc   = (const float*)d_in[p + 9];
    const float* wfc2  = (const float*)d_in[p + 10];
    const float* bfc2  = (const float*)d_in[p + 11];
    float* out = (float*)d_out;

    float *x1, *qkvp, *att, *h, *x2, *ffn, *pm, *ps, *pa;
    cudaGetSymbolAddress((void**)&x1,   g_x1);
    cudaGetSymbolAddress((void**)&qkvp, g_qkv);
    cudaGetSymbolAddress((void**)&att,  g_att);
    cudaGetSymbolAddress((void**)&h,    g_h);
    cudaGetSymbolAddress((void**)&x2,   g_x2);
    cudaGetSymbolAddress((void**)&ffn,  g_ffn);
    cudaGetSymbolAddress((void**)&pm,   g_pm);
    cudaGetSymbolAddress((void**)&ps,   g_ps);
    cudaGetSymbolAddress((void**)&pa,   g_pa);

    cudaFuncSetAttribute(gemm_tc,
        cudaFuncAttributeMaxDynamicSharedMemorySize, GEMM_SMEM);

    // 1. ln1 + merged bias/residual inits
    ln_kernel<<<BATCH, 256>>>(hidden, ln1g, ln1b, x1);
    init3_kernel<<<512, 256>>>(qkvp, battn, h, bproj, hidden, ffn, bfc);
    // 2. qkv = x1 @ w_attn + b_attn   (48 x 16 = 768 blocks, kc=128)
    gemm_tc<<<dim3(QKV_N / TN, 16), 256, GEMM_SMEM>>>(x1, wattn, qkvp, HDIM, QKV_N);
    // 3. attention (flash-decode, 32-way page split, V cp.async overlap)
    attn_partial<<<dim3(BATCH, NHEADS, NSPLIT), 256>>>(qkvp, kv, bt, sl, pm, ps, pa);
    attn_combine<<<dim3(BATCH, NHEADS), 128>>>(pm, ps, pa, att);
    // 4. h += attn @ w_proj   (16 x 32 = 512 blocks, kc=64)
    gemm_tc<<<dim3(HDIM / TN, 32), 256, GEMM_SMEM>>>(att, wproj, h, HDIM, HDIM);
    // 5. ln2
    ln_kernel<<<BATCH, 256>>>(h, ln2g, ln2b, x2);
    // 6. ffn += x2 @ w_fc   (64 x 8 = 512 blocks, kc=256)
    gemm_tc<<<dim3(DFF / TN, 8), 256, GEMM_SMEM>>>(x2, wfc, ffn, HDIM, DFF);
    // 6b. gelu in place
    gelu_kernel<<<(BATCH * DFF / 4 + 255) / 256, 256>>>(ffn, BATCH * DFF / 4);
    // 7. out = h + b_fc2 + gelu(ffn) @ w_fc2   (16 x 32 = 512 blocks, kc=256)
    init_kernel<<<128, 256>>>(out, bfc2, h, HDIM, BATCH * HDIM);
    gemm_tc<<<dim3(HDIM / TN, 32), 256, GEMM_SMEM>>>(ffn, wfc2, out, DFF, HDIM);
}

// round 7
// speedup vs baseline: 1.1154x; 1.1154x over previous
#include <cuda_runtime.h>
#include <cuda_bf16.h>
#include <math.h>

// ---------------- constants ----------------
#define BATCH   32
#define HDIM    2048
#define NHEADS  16
#define HEADD   128
#define DFF     8192
#define QKV_N   (3*HDIM)   // 6144
#define MAXS    2048
#define MAXBLK  32
#define PAGE    64
#define NUMBLK  1024
#define NSPLIT  32
#define CHUNK   64         // MAXS / NSPLIT == one KV page
#define TKC     32         // gemm k-chunk
#define TN      128        // gemm n-tile
#define NSTAGE  4          // gemm pipeline stages

// ---------------- scratch (no allocs allowed) ----------------
__device__ float g_x1 [BATCH*HDIM];
__device__ float g_qkv[BATCH*QKV_N];
__device__ float g_att[BATCH*HDIM];
__device__ float g_h  [BATCH*HDIM];
__device__ float g_x2 [BATCH*HDIM];
__device__ float g_ffn[BATCH*DFF];
__device__ float g_pm [BATCH*NHEADS*NSPLIT];
__device__ float g_ps [BATCH*NHEADS*NSPLIT];
__device__ float g_pa [BATCH*NHEADS*NSPLIT*HEADD];

// ---------------- helpers ----------------
__device__ __forceinline__ float gelu_exact(float x) {
    return 0.5f * x * (1.0f + erff(x * 0.70710678118654752f));
}

// A split: hi = rna-tf32(x), lo = raw fp32 bits of (x - hi) (HW truncates to tf32)
__device__ __forceinline__ void split_tf32(float x, unsigned &hi, unsigned &lo) {
    unsigned h;
    asm("cvt.rna.tf32.f32 %0, %1;" : "=r"(h) : "f"(x));
    hi = h;
    lo = __float_as_uint(x - __uint_as_float(h));
}
// W: single unbiased rounding to tf32
__device__ __forceinline__ unsigned rna_tf32(float x) {
    unsigned h;
    asm("cvt.rna.tf32.f32 %0, %1;" : "=r"(h) : "f"(x));
    return h;
}

__device__ __forceinline__ void mma_tf32(float d[4], const unsigned a[4],
                                         unsigned b0, unsigned b1) {
    asm volatile(
        "mma.sync.aligned.m16n8k8.row.col.f32.tf32.tf32.f32 "
        "{%0,%1,%2,%3}, {%4,%5,%6,%7}, {%8,%9}, {%0,%1,%2,%3};"
        : "+f"(d[0]), "+f"(d[1]), "+f"(d[2]), "+f"(d[3])
        : "r"(a[0]), "r"(a[1]), "r"(a[2]), "r"(a[3]), "r"(b0), "r"(b1));
}

__device__ __forceinline__ void cp_async16(void* smem, const void* g) {
    unsigned s = (unsigned)__cvta_generic_to_shared(smem);
    asm volatile("cp.async.cg.shared.global [%0], [%1], 16;" :: "r"(s), "l"(g));
}
__device__ __forceinline__ void cp_commit() {
    asm volatile("cp.async.commit_group;");
}
template<int N>
__device__ __forceinline__ void cp_wait() {
    asm volatile("cp.async.wait_group %0;" :: "n"(N));
}

// ---------------- LayerNorm: 32 rows x 2048 ----------------
__global__ void __launch_bounds__(256) ln_kernel(
    const float* __restrict__ x, const float* __restrict__ g,
    const float* __restrict__ b, float* __restrict__ y)
{
    int row = blockIdx.x;
    const float* xr = x + row * HDIM;
    float s = 0.f, s2 = 0.f;
    for (int i = threadIdx.x; i < HDIM; i += 256) {
        float v = xr[i]; s += v; s2 += v * v;
    }
    __shared__ float sh[16];
    int lane = threadIdx.x & 31, w = threadIdx.x >> 5;
    #pragma unroll
    for (int o = 16; o; o >>= 1) {
        s  += __shfl_xor_sync(0xffffffffu, s,  o);
        s2 += __shfl_xor_sync(0xffffffffu, s2, o);
    }
    if (lane == 0) { sh[w] = s; sh[8 + w] = s2; }
    __syncthreads();
    if (threadIdx.x == 0) {
        float S = 0.f, S2 = 0.f;
        #pragma unroll
        for (int i = 0; i < 8; i++) { S += sh[i]; S2 += sh[8 + i]; }
        sh[0] = S; sh[1] = S2;
    }
    __syncthreads();
    float mu  = sh[0] * (1.0f / HDIM);
    float var = sh[1] * (1.0f / HDIM) - mu * mu;
    float inv = rsqrtf(var + 1e-5f);
    float* yr = y + row * HDIM;
    for (int i = threadIdx.x; i < HDIM; i += 256)
        yr[i] = (xr[i] - mu) * inv * g[i] + b[i];
}

// ---------------- merged init: qkv=b, h=b+res, ffn=b ----------------
__global__ void __launch_bounds__(256) init3_kernel(
    float* __restrict__ qkv, const float* __restrict__ battn,
    float* __restrict__ h, const float* __restrict__ bproj,
    const float* __restrict__ hidden,
    float* __restrict__ ffn, const float* __restrict__ bfc)
{
    const int n1 = BATCH * QKV_N;
    const int n2 = n1 + BATCH * HDIM;
    const int n3 = n2 + BATCH * DFF;
    for (int i = blockIdx.x * 256 + threadIdx.x; i < n3; i += gridDim.x * 256) {
        if (i < n1) {
            qkv[i] = battn[i % QKV_N];
        } else if (i < n2) {
            int j = i - n1;
            h[j] = bproj[j & (HDIM - 1)] + hidden[j];
        } else {
            int j = i - n2;
            ffn[j] = bfc[j & (DFF - 1)];
        }
    }
}

__global__ void init_kernel(float* __restrict__ C, const float* __restrict__ bias,
                            const float* __restrict__ res, int N, int total)
{
    for (int i = blockIdx.x * blockDim.x + threadIdx.x; i < total;
         i += gridDim.x * blockDim.x) {
        int col = i - (i / N) * N;
        float v = bias[col];
        if (res) v += res[i];
        C[i] = v;
    }
}

// ---------------- elementwise gelu (in place, float4) ----------------
__global__ void gelu_kernel(float* __restrict__ x, int n4)
{
    int i = blockIdx.x * 256 + threadIdx.x;
    if (i < n4) {
        float4 v = reinterpret_cast<float4*>(x)[i];
        v.x = gelu_exact(v.x); v.y = gelu_exact(v.y);
        v.z = gelu_exact(v.z); v.w = gelu_exact(v.w);
        reinterpret_cast<float4*>(x)[i] = v;
    }
}

// ---------------- tensor-core GEMM: C[32,N] += A[32,K] @ W[K,N] ----------------
// 2xTF32 (A hi/lo split, W rounded once), 4-stage cp.async ring, 2 CTAs/SM.
// 256 thr = 8 warps: 2(m16) x 4(n32). split-K via gridDim.y, atomicAdd into
// bias-preinitialized C.
#define WS_FL (TKC*136)
#define AS_FL (32*36)
#define GEMM_SMEM (NSTAGE*(WS_FL+AS_FL)*4)
__global__ void __launch_bounds__(256, 2) gemm_tc(
    const float* __restrict__ A, const float* __restrict__ W,
    float* __restrict__ C, int K, int N)
{
    extern __shared__ float smp[];
    float (*Ws)[TKC][136] = reinterpret_cast<float(*)[TKC][136]>(smp);
    float (*As)[32][36]   = reinterpret_cast<float(*)[32][36]>(smp + NSTAGE * WS_FL);

    int tid = threadIdx.x;
    int lane = tid & 31, warp = tid >> 5;
    int m0 = (warp & 1) * 16;
    int n0w = (warp >> 1) * 32;
    int nblk = blockIdx.x * TN;

    int kc = K / gridDim.y;
    int kbeg = blockIdx.y * kc;
    int nchunk = kc / TKC;

    float acc[4][4] = {};

    int am = tid >> 3, ak = (tid & 7) * 4;   // A staging coords (1 seg/thread)
    int gr = lane >> 2, kq = lane & 3;       // fragment coords

    auto prefetch = [&](int chunk) {
        int kb = kbeg + chunk * TKC;
        int s = chunk & (NSTAGE - 1);
        cp_async16(&As[s][am][ak], &A[am * K + kb + ak]);
        #pragma unroll
        for (int it = 0; it < 4; ++it) {
            int idx = it * 256 + tid;
            int kk = idx >> 5, c4 = (idx & 31) * 4;
            cp_async16(&Ws[s][kk][c4], &W[(size_t)(kb + kk) * N + nblk + c4]);
        }
    };

    #pragma unroll
    for (int c = 0; c < NSTAGE - 1; ++c) {
        if (c < nchunk) prefetch(c);
        cp_commit();
    }

    for (int i = 0; i < nchunk; ++i) {
        if (i + NSTAGE - 1 < nchunk) prefetch(i + NSTAGE - 1);
        cp_commit();
        cp_wait<NSTAGE - 1>();
        __syncthreads();
        int s = i & (NSTAGE - 1);
        #pragma unroll
        for (int ks = 0; ks < 4; ++ks) {
            int k0 = ks * 8;
            unsigned ah[4], al[4];
            split_tf32(As[s][m0 + gr    ][k0 + kq    ], ah[0], al[0]);
            split_tf32(As[s][m0 + gr + 8][k0 + kq    ], ah[1], al[1]);
            split_tf32(As[s][m0 + gr    ][k0 + kq + 4], ah[2], al[2]);
            split_tf32(As[s][m0 + gr + 8][k0 + kq + 4], ah[3], al[3]);
            #pragma unroll
            for (int nt = 0; nt < 4; ++nt) {
                int nb2 = n0w + nt * 8 + gr;
                unsigned bh0 = rna_tf32(Ws[s][k0 + kq    ][nb2]);
                unsigned bh1 = rna_tf32(Ws[s][k0 + kq + 4][nb2]);
                mma_tf32(acc[nt], ah, bh0, bh1);
                mma_tf32(acc[nt], al, bh0, bh1);
            }
        }
        __syncthreads();   // all reads done before ring slot is overwritten
    }

    int cq = (lane & 3) * 2;
    #pragma unroll
    for (int nt = 0; nt < 4; ++nt) {
        int col = nblk + n0w + nt * 8 + cq;
        atomicAdd(&C[(m0 + gr    ) * N + col    ], acc[nt][0]);
        atomicAdd(&C[(m0 + gr    ) * N + col + 1], acc[nt][1]);
        atomicAdd(&C[(m0 + gr + 8) * N + col    ], acc[nt][2]);
        atomicAdd(&C[(m0 + gr + 8) * N + col + 1], acc[nt][3]);
    }
}

// ---------------- attention partial: one block per (b,h,page) ----------------
__global__ void __launch_bounds__(256) attn_partial(
    const float* __restrict__ qkv, const float* __restrict__ kv,
    const int* __restrict__ bt, const int* __restrict__ sl,
    float* __restrict__ pm, float* __restrict__ ps, float* __restrict__ pa)
{
    int b = blockIdx.x, h = blockIdx.y, sp = blockIdx.z;
    int tid = threadIdx.x, lane = tid & 31, w = tid >> 5;
    int pidx = (b * NHEADS + h) * NSPLIT + sp;
    int seq = sl[b];
    int t0 = sp * CHUNK;
    if (t0 >= seq) {
        if (tid == 0) { pm[pidx] = -INFINITY; ps[pidx] = 0.f; }
        return;
    }
    int nt = seq - t0; if (nt > CHUNK) nt = CHUNK;

    __shared__ float qs[HEADD];
    __shared__ float sc[CHUNK];
    __shared__ int   rbs;              // page base (float index, < 2^31)
    __shared__ float red[9];
    __shared__ float sa[2][HEADD];

    if (tid < HEADD) qs[tid] = qkv[b * QKV_N + h * HEADD + tid];
    if (tid == 0)
        rbs = bt[b * MAXBLK + sp] * (PAGE * NHEADS * HEADD) + h * HEADD;
    __syncthreads();
    int rb = rbs;

    const float scale = 0.08838834764831845f;  // 1/sqrt(128)
    float4 qx = reinterpret_cast<const float4*>(qs)[lane];

    // pass 1: scores. 8 warps, 2 tokens/warp/iter, full-warp shfl reduce.
    for (int t = w * 2; t < nt; t += 16) {
        const float* k0p = kv + rb + t * (NHEADS * HEADD);
        float4 ka = reinterpret_cast<const float4*>(k0p)[lane];
        bool two = (t + 1) < nt;
        const float* k1p = k0p + (NHEADS * HEADD);
        float4 kb2 = two ? reinterpret_cast<const float4*>(k1p)[lane] : ka;
        float d0 = ka.x * qx.x + ka.y * qx.y + ka.z * qx.z + ka.w * qx.w;
        float d1 = kb2.x * qx.x + kb2.y * qx.y + kb2.z * qx.z + kb2.w * qx.w;
        #pragma unroll
        for (int o = 16; o; o >>= 1) {
            d0 += __shfl_xor_sync(0xffffffffu, d0, o);
            d1 += __shfl_xor_sync(0xffffffffu, d1, o);
        }
        if (lane == 0) {
            sc[t] = d0 * scale;
            if (two) sc[t + 1] = d1 * scale;
        }
    }
    __syncthreads();

    // local max
    float m = -INFINITY;
    if (tid < nt) m = sc[tid];
    #pragma unroll
    for (int o = 16; o; o >>= 1) m = fmaxf(m, __shfl_xor_sync(0xffffffffu, m, o));
    if (lane == 0) red[w] = m;
    __syncthreads();
    if (tid == 0) {
        float mm = red[0];
        #pragma unroll
        for (int i = 1; i < 8; i++) mm = fmaxf(mm, red[i]);
        red[8] = mm;
    }
    __syncthreads();
    float M = red[8];
    __syncthreads();

    // exp + local sum
    float s = 0.f;
    if (tid < nt) {
        float e = __expf(sc[tid] - M);
        sc[tid] = e; s = e;
    }
    #pragma unroll
    for (int o = 16; o; o >>= 1) s += __shfl_xor_sync(0xffffffffu, s, o);
    if (lane == 0) red[w] = s;
    __syncthreads();
    if (tid == 0) {
        float S = 0.f;
        #pragma unroll
        for (int i = 0; i < 8; i++) S += red[i];
        pm[pidx] = M; ps[pidx] = S;
    }

    // pass 2: unnormalized weighted V. 2 halves x 4-way unroll.
    int d = tid & 127, half = tid >> 7;
    const float* Vb = kv + (size_t)NUMBLK * PAGE * NHEADS * HEADD;
    float a0 = 0.f, a1 = 0.f, a2 = 0.f, a3 = 0.f;
    int t = half;
    for (; t + 6 < nt; t += 8) {
        const float* v0 = Vb + rb + (t    ) * (NHEADS * HEADD);
        const float* v1 = Vb + rb + (t + 2) * (NHEADS * HEADD);
        const float* v2 = Vb + rb + (t + 4) * (NHEADS * HEADD);
        const float* v3 = Vb + rb + (t + 6) * (NHEADS * HEADD);
        a0 += sc[t    ] * v0[d];
        a1 += sc[t + 2] * v1[d];
        a2 += sc[t + 4] * v2[d];
        a3 += sc[t + 6] * v3[d];
    }
    for (; t < nt; t += 2) {
        const float* vr = Vb + rb + t * (NHEADS * HEADD);
        a0 += sc[t] * vr[d];
    }
    sa[half][d] = (a0 + a1) + (a2 + a3);
    __syncthreads();
    if (tid < HEADD) pa[(size_t)pidx * HEADD + tid] = sa[0][tid] + sa[1][tid];
}

// ---------------- attention combine: one block per (b,h) ----------------
__global__ void __launch_bounds__(128) attn_combine(
    const float* __restrict__ pm, const float* __restrict__ ps,
    const float* __restrict__ pa, float* __restrict__ out)
{
    int b = blockIdx.x, h = blockIdx.y;
    int idx = b * NHEADS + h;
    int tid = threadIdx.x;
    __shared__ float ms[NSPLIT], ss[NSPLIT];
    if (tid < NSPLIT) {
        ms[tid] = pm[idx * NSPLIT + tid];
        ss[tid] = ps[idx * NSPLIT + tid];
    }
    __syncthreads();
    float M = -INFINITY;
    #pragma unroll
    for (int i = 0; i < NSPLIT; i++)
        if (ss[i] > 0.f) M = fmaxf(M, ms[i]);
    float num = 0.f, den = 0.f;
    #pragma unroll
    for (int i = 0; i < NSPLIT; i++) {
        if (ss[i] > 0.f) {
            float wv = __expf(ms[i] - M);
            den += wv * ss[i];
            num += wv * pa[((size_t)idx * NSPLIT + i) * HEADD + tid];
        }
    }
    out[b * HDIM + h * HEADD + tid] = num / den;
}

// ---------------- host launcher ----------------
extern "C" void kernel_launch(void* const* d_in, const int* in_sizes, int n_in,
                              void* d_out, int out_size)
{
    const float* hidden = (const float*)d_in[0];
    const float* kv     = (const float*)d_in[1];
    const int*   bt     = (const int*)d_in[2];
    const int*   sl     = (const int*)d_in[3];
    int p = (n_in > 4 && in_sizes[4] == 1) ? 5 : 4;  // skip max_seq_len if present
    const float* ln1g  = (const float*)d_in[p + 0];
    const float* ln1b  = (const float*)d_in[p + 1];
    const float* ln2g  = (const float*)d_in[p + 2];
    const float* ln2b  = (const float*)d_in[p + 3];
    const float* wattn = (const float*)d_in[p + 4];
    const float* battn = (const float*)d_in[p + 5];
    const float* wproj = (const float*)d_in[p + 6];
    const float* bproj = (const float*)d_in[p + 7];
    const float* wfc   = (const float*)d_in[p + 8];
    const float* bfc   = (const float*)d_in[p + 9];
    const float* wfc2  = (const float*)d_in[p + 10];
    const float* bfc2  = (const float*)d_in[p + 11];
    float* out = (float*)d_out;

    float *x1, *qkvp, *att, *h, *x2, *ffn, *pm, *ps, *pa;
    cudaGetSymbolAddress((void**)&x1,   g_x1);
    cudaGetSymbolAddress((void**)&qkvp, g_qkv);
    cudaGetSymbolAddress((void**)&att,  g_att);
    cudaGetSymbolAddress((void**)&h,    g_h);
    cudaGetSymbolAddress((void**)&x2,   g_x2);
    cudaGetSymbolAddress((void**)&ffn,  g_ffn);
    cudaGetSymbolAddress((void**)&pm,   g_pm);
    cudaGetSymbolAddress((void**)&ps,   g_ps);
    cudaGetSymbolAddress((void**)&pa,   g_pa);

    cudaFuncSetAttribute(gemm_tc,
        cudaFuncAttributeMaxDynamicSharedMemorySize, GEMM_SMEM);

    // 1. ln1 + merged bias/residual inits
    ln_kernel<<<BATCH, 256>>>(hidden, ln1g, ln1b, x1);
    init3_kernel<<<512, 256>>>(qkvp, battn, h, bproj, hidden, ffn, bfc);
    // 2. qkv = x1 @ w_attn + b_attn   (48 x 8 = 384 blocks, kc=256)
    gemm_tc<<<dim3(QKV_N / TN, 8), 256, GEMM_SMEM>>>(x1, wattn, qkvp, HDIM, QKV_N);
    // 3. attention (flash-decode, 32-way page split)
    attn_partial<<<dim3(BATCH, NHEADS, NSPLIT), 256>>>(qkvp, kv, bt, sl, pm, ps, pa);
    attn_combine<<<dim3(BATCH, NHEADS), 128>>>(pm, ps, pa, att);
    // 4. h += attn @ w_proj   (16 x 16 = 256 blocks, kc=128)
    gemm_tc<<<dim3(HDIM / TN, 16), 256, GEMM_SMEM>>>(att, wproj, h, HDIM, HDIM);
    // 5. ln2
    ln_kernel<<<BATCH, 256>>>(h, ln2g, ln2b, x2);
    // 6. ffn += x2 @ w_fc   (64 x 8 = 512 blocks, kc=256)
    gemm_tc<<<dim3(DFF / TN, 8), 256, GEMM_SMEM>>>(x2, wfc, ffn, HDIM, DFF);
    // 6b. gelu in place
    gelu_kernel<<<(BATCH * DFF / 4 + 255) / 256, 256>>>(ffn, BATCH * DFF / 4);
    // 7. out = h + b_fc2 + gelu(ffn) @ w_fc2   (16 x 32 = 512 blocks, kc=256)
    init_kernel<<<128, 256>>>(out, bfc2, h, HDIM, BATCH * HDIM);
    gemm_tc<<<dim3(HDIM / TN, 32), 256, GEMM_SMEM>>>(ffn, wfc2, out, DFF, HDIM);
}

// round 8
// speedup vs baseline: 1.1955x; 1.0718x over previous
#include <cuda_runtime.h>
#include <cuda_bf16.h>
#include <math.h>

// ---------------- constants ----------------
#define BATCH   32
#define HDIM    2048
#define NHEADS  16
#define HEADD   128
#define DFF     8192
#define QKV_N   (3*HDIM)   // 6144
#define MAXS    2048
#define MAXBLK  32
#define PAGE    64
#define NUMBLK  1024
#define NSPLIT  32
#define CHUNK   64         // MAXS / NSPLIT == one KV page
#define TKC     32         // gemm k-chunk
#define TN      128        // gemm n-tile
#define NSTAGE  4          // gemm pipeline stages

// ---------------- scratch (no allocs allowed) ----------------
__device__ float g_x1 [BATCH*HDIM];
__device__ float g_qkv[BATCH*QKV_N];
__device__ float g_att[BATCH*HDIM];
__device__ float g_h  [BATCH*HDIM];
__device__ float g_x2 [BATCH*HDIM];
__device__ float g_ffn[BATCH*DFF];
__device__ float g_pm [BATCH*NHEADS*NSPLIT];
__device__ float g_ps [BATCH*NHEADS*NSPLIT];
__device__ float g_pa [BATCH*NHEADS*NSPLIT*HEADD];

// ---------------- helpers ----------------
__device__ __forceinline__ float gelu_exact(float x) {
    return 0.5f * x * (1.0f + erff(x * 0.70710678118654752f));
}

// A split: hi = rna-tf32(x), lo = x - hi (exact; HW truncates lo to tf32)
__device__ __forceinline__ void split_tf32(float x, unsigned &hi, unsigned &lo) {
    unsigned h;
    asm("cvt.rna.tf32.f32 %0, %1;" : "=r"(h) : "f"(x));
    hi = h;
    lo = __float_as_uint(x - __uint_as_float(h));
}
// W: single unbiased rounding to tf32
__device__ __forceinline__ unsigned rna_tf32(float x) {
    unsigned h;
    asm("cvt.rna.tf32.f32 %0, %1;" : "=r"(h) : "f"(x));
    return h;
}

__device__ __forceinline__ void mma_tf32(float d[4], const unsigned a[4],
                                         unsigned b0, unsigned b1) {
    asm volatile(
        "mma.sync.aligned.m16n8k8.row.col.f32.tf32.tf32.f32 "
        "{%0,%1,%2,%3}, {%4,%5,%6,%7}, {%8,%9}, {%0,%1,%2,%3};"
        : "+f"(d[0]), "+f"(d[1]), "+f"(d[2]), "+f"(d[3])
        : "r"(a[0]), "r"(a[1]), "r"(a[2]), "r"(a[3]), "r"(b0), "r"(b1));
}

__device__ __forceinline__ void cp_async16(void* smem, const void* g) {
    unsigned s = (unsigned)__cvta_generic_to_shared(smem);
    asm volatile("cp.async.cg.shared.global [%0], [%1], 16;" :: "r"(s), "l"(g));
}
__device__ __forceinline__ void cp_commit() {
    asm volatile("cp.async.commit_group;");
}
template<int N>
__device__ __forceinline__ void cp_wait() {
    asm volatile("cp.async.wait_group %0;" :: "n"(N));
}

// ---------------- LayerNorm: 32 rows x 2048 ----------------
__global__ void __launch_bounds__(256) ln_kernel(
    const float* __restrict__ x, const float* __restrict__ g,
    const float* __restrict__ b, float* __restrict__ y)
{
    int row = blockIdx.x;
    const float* xr = x + row * HDIM;
    float s = 0.f, s2 = 0.f;
    for (int i = threadIdx.x; i < HDIM; i += 256) {
        float v = xr[i]; s += v; s2 += v * v;
    }
    __shared__ float sh[16];
    int lane = threadIdx.x & 31, w = threadIdx.x >> 5;
    #pragma unroll
    for (int o = 16; o; o >>= 1) {
        s  += __shfl_xor_sync(0xffffffffu, s,  o);
        s2 += __shfl_xor_sync(0xffffffffu, s2, o);
    }
    if (lane == 0) { sh[w] = s; sh[8 + w] = s2; }
    __syncthreads();
    if (threadIdx.x == 0) {
        float S = 0.f, S2 = 0.f;
        #pragma unroll
        for (int i = 0; i < 8; i++) { S += sh[i]; S2 += sh[8 + i]; }
        sh[0] = S; sh[1] = S2;
    }
    __syncthreads();
    float mu  = sh[0] * (1.0f / HDIM);
    float var = sh[1] * (1.0f / HDIM) - mu * mu;
    float inv = rsqrtf(var + 1e-5f);
    float* yr = y + row * HDIM;
    for (int i = threadIdx.x; i < HDIM; i += 256)
        yr[i] = (xr[i] - mu) * inv * g[i] + b[i];
}

// ---------------- merged init: qkv=b, h=b+res, ffn=b ----------------
__global__ void __launch_bounds__(256) init3_kernel(
    float* __restrict__ qkv, const float* __restrict__ battn,
    float* __restrict__ h, const float* __restrict__ bproj,
    const float* __restrict__ hidden,
    float* __restrict__ ffn, const float* __restrict__ bfc)
{
    const int n1 = BATCH * QKV_N;
    const int n2 = n1 + BATCH * HDIM;
    const int n3 = n2 + BATCH * DFF;
    for (int i = blockIdx.x * 256 + threadIdx.x; i < n3; i += gridDim.x * 256) {
        if (i < n1) {
            qkv[i] = battn[i % QKV_N];
        } else if (i < n2) {
            int j = i - n1;
            h[j] = bproj[j & (HDIM - 1)] + hidden[j];
        } else {
            int j = i - n2;
            ffn[j] = bfc[j & (DFF - 1)];
        }
    }
}

// ---------------- fc2 prep: gelu(ffn) in place + out = h + b_fc2 ----------------
__global__ void __launch_bounds__(256) prep_fc2_kernel(
    float* __restrict__ ffn, float* __restrict__ out,
    const float* __restrict__ h, const float* __restrict__ bfc2)
{
    const int n1 = BATCH * DFF / 4;                 // gelu range (float4)
    const int n2 = n1 + BATCH * HDIM;               // out-init range (scalar)
    for (int i = blockIdx.x * 256 + threadIdx.x; i < n2; i += gridDim.x * 256) {
        if (i < n1) {
            float4 v = reinterpret_cast<float4*>(ffn)[i];
            v.x = gelu_exact(v.x); v.y = gelu_exact(v.y);
            v.z = gelu_exact(v.z); v.w = gelu_exact(v.w);
            reinterpret_cast<float4*>(ffn)[i] = v;
        } else {
            int j = i - n1;
            out[j] = h[j] + bfc2[j & (HDIM - 1)];
        }
    }
}

// ---------------- tensor-core GEMM: C[32,N] += A[32,K] @ W[K,N] ----------------
// 2xTF32 (A hi/lo split, W rounded once), 4-stage cp.async ring, 2 CTAs/SM,
// ONE barrier per chunk (prefetch placed after the barrier: slot (i-1)%4 is
// provably drained). split-K via gridDim.y, atomicAdd into preinit C.
#define WS_FL (TKC*136)
#define AS_FL (32*36)
#define GEMM_SMEM (NSTAGE*(WS_FL+AS_FL)*4)
__global__ void __launch_bounds__(256, 2) gemm_tc(
    const float* __restrict__ A, const float* __restrict__ W,
    float* __restrict__ C, int K, int N)
{
    extern __shared__ float smp[];
    float (*Ws)[TKC][136] = reinterpret_cast<float(*)[TKC][136]>(smp);
    float (*As)[32][36]   = reinterpret_cast<float(*)[32][36]>(smp + NSTAGE * WS_FL);

    int tid = threadIdx.x;
    int lane = tid & 31, warp = tid >> 5;
    int m0 = (warp & 1) * 16;
    int n0w = (warp >> 1) * 32;
    int nblk = blockIdx.x * TN;

    int kc = K / gridDim.y;
    int kbeg = blockIdx.y * kc;
    int nchunk = kc / TKC;

    float acc[4][4] = {};

    int am = tid >> 3, ak = (tid & 7) * 4;   // A staging coords (1 seg/thread)
    int gr = lane >> 2, kq = lane & 3;       // fragment coords

    auto prefetch = [&](int chunk) {
        int kb = kbeg + chunk * TKC;
        int s = chunk & (NSTAGE - 1);
        cp_async16(&As[s][am][ak], &A[am * K + kb + ak]);
        #pragma unroll
        for (int it = 0; it < 4; ++it) {
            int idx = it * 256 + tid;
            int kk = idx >> 5, c4 = (idx & 31) * 4;
            cp_async16(&Ws[s][kk][c4], &W[(size_t)(kb + kk) * N + nblk + c4]);
        }
    };

    #pragma unroll
    for (int c = 0; c < NSTAGE - 1; ++c) {
        if (c < nchunk) prefetch(c);
        cp_commit();
    }

    for (int i = 0; i < nchunk; ++i) {
        cp_wait<NSTAGE - 2>();    // group i complete
        __syncthreads();          // all warps done with compute(i-1) and see stage i
        if (i + NSTAGE - 1 < nchunk) prefetch(i + NSTAGE - 1);
        cp_commit();
        int s = i & (NSTAGE - 1);
        #pragma unroll
        for (int ks = 0; ks < 4; ++ks) {
            int k0 = ks * 8;
            unsigned ah[4], al[4];
            split_tf32(As[s][m0 + gr    ][k0 + kq    ], ah[0], al[0]);
            split_tf32(As[s][m0 + gr + 8][k0 + kq    ], ah[1], al[1]);
            split_tf32(As[s][m0 + gr    ][k0 + kq + 4], ah[2], al[2]);
            split_tf32(As[s][m0 + gr + 8][k0 + kq + 4], ah[3], al[3]);
            #pragma unroll
            for (int nt = 0; nt < 4; ++nt) {
                int nb2 = n0w + nt * 8 + gr;
                unsigned bh0 = rna_tf32(Ws[s][k0 + kq    ][nb2]);
                unsigned bh1 = rna_tf32(Ws[s][k0 + kq + 4][nb2]);
                mma_tf32(acc[nt], ah, bh0, bh1);
                mma_tf32(acc[nt], al, bh0, bh1);
            }
        }
    }

    int cq = (lane & 3) * 2;
    #pragma unroll
    for (int nt = 0; nt < 4; ++nt) {
        int col = nblk + n0w + nt * 8 + cq;
        atomicAdd(&C[(m0 + gr    ) * N + col    ], acc[nt][0]);
        atomicAdd(&C[(m0 + gr    ) * N + col + 1], acc[nt][1]);
        atomicAdd(&C[(m0 + gr + 8) * N + col    ], acc[nt][2]);
        atomicAdd(&C[(m0 + gr + 8) * N + col + 1], acc[nt][3]);
    }
}

// ---------------- attention partial: one block per (b,h,page) ----------------
__global__ void __launch_bounds__(256) attn_partial(
    const float* __restrict__ qkv, const float* __restrict__ kv,
    const int* __restrict__ bt, const int* __restrict__ sl,
    float* __restrict__ pm, float* __restrict__ ps, float* __restrict__ pa)
{
    int b = blockIdx.x, h = blockIdx.y, sp = blockIdx.z;
    int tid = threadIdx.x, lane = tid & 31, w = tid >> 5;
    int pidx = (b * NHEADS + h) * NSPLIT + sp;
    int seq = sl[b];
    int t0 = sp * CHUNK;
    if (t0 >= seq) {
        if (tid == 0) { pm[pidx] = -INFINITY; ps[pidx] = 0.f; }
        return;
    }
    int nt = seq - t0; if (nt > CHUNK) nt = CHUNK;

    __shared__ float qs[HEADD];
    __shared__ float sc[CHUNK];
    __shared__ int   rbs;              // page base (float index, < 2^31)
    __shared__ float red[9];
    __shared__ float sa[2][HEADD];

    if (tid < HEADD) qs[tid] = qkv[b * QKV_N + h * HEADD + tid];
    if (tid == 0)
        rbs = bt[b * MAXBLK + sp] * (PAGE * NHEADS * HEADD) + h * HEADD;
    __syncthreads();
    int rb = rbs;

    const float scale = 0.08838834764831845f;  // 1/sqrt(128)
    float4 qx = reinterpret_cast<const float4*>(qs)[lane];

    // pass 1: scores. 4 tokens/warp/iter (loads clamped to page row 63 — always
    // resident; stores guarded by nt). Interleaved shfl chains pipeline.
    for (int tb = w * 4; tb < nt; tb += 32) {
        int u1 = min(tb + 1, 63), u2 = min(tb + 2, 63), u3 = min(tb + 3, 63);
        const float* base = kv + rb;
        float4 ka = reinterpret_cast<const float4*>(base + tb * (NHEADS * HEADD))[lane];
        float4 kb2 = reinterpret_cast<const float4*>(base + u1 * (NHEADS * HEADD))[lane];
        float4 kc2 = reinterpret_cast<const float4*>(base + u2 * (NHEADS * HEADD))[lane];
        float4 kd2 = reinterpret_cast<const float4*>(base + u3 * (NHEADS * HEADD))[lane];
        float d0 = ka.x  * qx.x + ka.y  * qx.y + ka.z  * qx.z + ka.w  * qx.w;
        float d1 = kb2.x * qx.x + kb2.y * qx.y + kb2.z * qx.z + kb2.w * qx.w;
        float d2 = kc2.x * qx.x + kc2.y * qx.y + kc2.z * qx.z + kc2.w * qx.w;
        float d3 = kd2.x * qx.x + kd2.y * qx.y + kd2.z * qx.z + kd2.w * qx.w;
        #pragma unroll
        for (int o = 16; o; o >>= 1) {
            d0 += __shfl_xor_sync(0xffffffffu, d0, o);
            d1 += __shfl_xor_sync(0xffffffffu, d1, o);
            d2 += __shfl_xor_sync(0xffffffffu, d2, o);
            d3 += __shfl_xor_sync(0xffffffffu, d3, o);
        }
        if (lane == 0) {
            sc[tb] = d0 * scale;
            if (tb + 1 < nt) sc[tb + 1] = d1 * scale;
            if (tb + 2 < nt) sc[tb + 2] = d2 * scale;
            if (tb + 3 < nt) sc[tb + 3] = d3 * scale;
        }
    }
    __syncthreads();

    // local max
    float m = -INFINITY;
    if (tid < nt) m = sc[tid];
    #pragma unroll
    for (int o = 16; o; o >>= 1) m = fmaxf(m, __shfl_xor_sync(0xffffffffu, m, o));
    if (lane == 0) red[w] = m;
    __syncthreads();
    if (tid == 0) {
        float mm = red[0];
        #pragma unroll
        for (int i = 1; i < 8; i++) mm = fmaxf(mm, red[i]);
        red[8] = mm;
    }
    __syncthreads();
    float M = red[8];
    __syncthreads();

    // exp + local sum
    float s = 0.f;
    if (tid < nt) {
        float e = __expf(sc[tid] - M);
        sc[tid] = e; s = e;
    }
    #pragma unroll
    for (int o = 16; o; o >>= 1) s += __shfl_xor_sync(0xffffffffu, s, o);
    if (lane == 0) red[w] = s;
    __syncthreads();
    if (tid == 0) {
        float S = 0.f;
        #pragma unroll
        for (int i = 0; i < 8; i++) S += red[i];
        pm[pidx] = M; ps[pidx] = S;
    }

    // pass 2: unnormalized weighted V. 2 halves x 4-way unroll.
    int d = tid & 127, half = tid >> 7;
    const float* Vb = kv + (size_t)NUMBLK * PAGE * NHEADS * HEADD;
    float a0 = 0.f, a1 = 0.f, a2 = 0.f, a3 = 0.f;
    int t = half;
    for (; t + 6 < nt; t += 8) {
        const float* v0 = Vb + rb + (t    ) * (NHEADS * HEADD);
        const float* v1 = Vb + rb + (t + 2) * (NHEADS * HEADD);
        const float* v2 = Vb + rb + (t + 4) * (NHEADS * HEADD);
        const float* v3 = Vb + rb + (t + 6) * (NHEADS * HEADD);
        a0 += sc[t    ] * v0[d];
        a1 += sc[t + 2] * v1[d];
        a2 += sc[t + 4] * v2[d];
        a3 += sc[t + 6] * v3[d];
    }
    for (; t < nt; t += 2) {
        const float* vr = Vb + rb + t * (NHEADS * HEADD);
        a0 += sc[t] * vr[d];
    }
    sa[half][d] = (a0 + a1) + (a2 + a3);
    __syncthreads();
    if (tid < HEADD) pa[(size_t)pidx * HEADD + tid] = sa[0][tid] + sa[1][tid];
}

// ---------------- attention combine: one block per (b,h) ----------------
__global__ void __launch_bounds__(128) attn_combine(
    const float* __restrict__ pm, const float* __restrict__ ps,
    const float* __restrict__ pa, float* __restrict__ out)
{
    int b = blockIdx.x, h = blockIdx.y;
    int idx = b * NHEADS + h;
    int tid = threadIdx.x;
    __shared__ float ms[NSPLIT], ss[NSPLIT];
    if (tid < NSPLIT) {
        ms[tid] = pm[idx * NSPLIT + tid];
        ss[tid] = ps[idx * NSPLIT + tid];
    }
    __syncthreads();
    float M = -INFINITY;
    #pragma unroll
    for (int i = 0; i < NSPLIT; i++)
        if (ss[i] > 0.f) M = fmaxf(M, ms[i]);
    float num = 0.f, den = 0.f;
    #pragma unroll
    for (int i = 0; i < NSPLIT; i++) {
        if (ss[i] > 0.f) {
            float wv = __expf(ms[i] - M);
            den += wv * ss[i];
            num += wv * pa[((size_t)idx * NSPLIT + i) * HEADD + tid];
        }
    }
    out[b * HDIM + h * HEADD + tid] = num / den;
}

// ---------------- host launcher ----------------
extern "C" void kernel_launch(void* const* d_in, const int* in_sizes, int n_in,
                              void* d_out, int out_size)
{
    const float* hidden = (const float*)d_in[0];
    const float* kv     = (const float*)d_in[1];
    const int*   bt     = (const int*)d_in[2];
    const int*   sl     = (const int*)d_in[3];
    int p = (n_in > 4 && in_sizes[4] == 1) ? 5 : 4;  // skip max_seq_len if present
    const float* ln1g  = (const float*)d_in[p + 0];
    const float* ln1b  = (const float*)d_in[p + 1];
    const float* ln2g  = (const float*)d_in[p + 2];
    const float* ln2b  = (const float*)d_in[p + 3];
    const float* wattn = (const float*)d_in[p + 4];
    const float* battn = (const float*)d_in[p + 5];
    const float* wproj = (const float*)d_in[p + 6];
    const float* bproj = (const float*)d_in[p + 7];
    const float* wfc   = (const float*)d_in[p + 8];
    const float* bfc   = (const float*)d_in[p + 9];
    const float* wfc2  = (const float*)d_in[p + 10];
    const float* bfc2  = (const float*)d_in[p + 11];
    float* out = (float*)d_out;

    float *x1, *qkvp, *att, *h, *x2, *ffn, *pm, *ps, *pa;
    cudaGetSymbolAddress((void**)&x1,   g_x1);
    cudaGetSymbolAddress((void**)&qkvp, g_qkv);
    cudaGetSymbolAddress((void**)&att,  g_att);
    cudaGetSymbolAddress((void**)&h,    g_h);
    cudaGetSymbolAddress((void**)&x2,   g_x2);
    cudaGetSymbolAddress((void**)&ffn,  g_ffn);
    cudaGetSymbolAddress((void**)&pm,   g_pm);
    cudaGetSymbolAddress((void**)&ps,   g_ps);
    cudaGetSymbolAddress((void**)&pa,   g_pa);

    cudaFuncSetAttribute(gemm_tc,
        cudaFuncAttributeMaxDynamicSharedMemorySize, GEMM_SMEM);

    // 1. ln1 + merged bias/residual inits
    ln_kernel<<<BATCH, 256>>>(hidden, ln1g, ln1b, x1);
    init3_kernel<<<512, 256>>>(qkvp, battn, h, bproj, hidden, ffn, bfc);
    // 2. qkv = x1 @ w_attn + b_attn   (48 x 8 = 384 blocks, kc=256)
    gemm_tc<<<dim3(QKV_N / TN, 8), 256, GEMM_SMEM>>>(x1, wattn, qkvp, HDIM, QKV_N);
    // 3. attention (flash-decode, 32-way page split)
    attn_partial<<<dim3(BATCH, NHEADS, NSPLIT), 256>>>(qkvp, kv, bt, sl, pm, ps, pa);
    attn_combine<<<dim3(BATCH, NHEADS), 128>>>(pm, ps, pa, att);
    // 4. h += attn @ w_proj   (16 x 16 = 256 blocks, kc=128)
    gemm_tc<<<dim3(HDIM / TN, 16), 256, GEMM_SMEM>>>(att, wproj, h, HDIM, HDIM);
    // 5. ln2
    ln_kernel<<<BATCH, 256>>>(h, ln2g, ln2b, x2);
    // 6. ffn += x2 @ w_fc   (64 x 8 = 512 blocks, kc=256)
    gemm_tc<<<dim3(DFF / TN, 8), 256, GEMM_SMEM>>>(x2, wfc, ffn, HDIM, DFF);
    // 6b. gelu(ffn) + out = h + b_fc2 (one kernel)
    prep_fc2_kernel<<<296, 256>>>(ffn, out, h, bfc2);
    // 7. out += gelu(ffn) @ w_fc2   (16 x 16 = 256 blocks, kc=512)
    gemm_tc<<<dim3(HDIM / TN, 16), 256, GEMM_SMEM>>>(ffn, wfc2, out, DFF, HDIM);
}